// round 1
// baseline (speedup 1.0000x reference)
#include <cuda_runtime.h>
#include <math.h>

#define BB 2
#define TT 1024
#define DD 128
#define HH 64
// DH = 2

// Scratch (allocation-free contract: __device__ globals)
__device__ float g_Q[BB*TT*DD];
__device__ float g_K[BB*TT*DD];
__device__ float g_V[BB*TT*DD];
__device__ float g_AO[BB*TT*DD];

__device__ __forceinline__ float ex2f(float x) {
    float y;
    asm("ex2.approx.ftz.f32 %0, %1;" : "=f"(y) : "f"(x));
    return y;
}

// ---------------------------------------------------------------------------
// Tiled GEMM: C[2048 x 128] = A[2048 x 128] @ W[128 x 128]^T
// 64x64 output tile per block, BK=32, 256 threads, 4x4 micro-tile.
// Shared padded to 33 floats/row -> conflict-free scalar LDS.
// ---------------------------------------------------------------------------
__device__ __forceinline__ void gemm_tile(const float* __restrict__ A,
                                          const float* __restrict__ W,
                                          float* __restrict__ C) {
    __shared__ float As[64][33];
    __shared__ float Bs[64][33];
    const int tid = threadIdx.x;
    const int tx = tid & 15;
    const int ty = tid >> 4;
    const int rowBase = blockIdx.x * 64;
    const int colBase = blockIdx.y * 64;

    float acc[4][4];
    #pragma unroll
    for (int i = 0; i < 4; i++)
        #pragma unroll
        for (int j = 0; j < 4; j++) acc[i][j] = 0.f;

    for (int k0 = 0; k0 < 128; k0 += 32) {
        #pragma unroll
        for (int i = 0; i < 8; i++) {
            int idx = tid + i * 256;           // 2048 elements / 256 threads
            int r = idx >> 5;
            int c = idx & 31;
            As[r][c] = A[(rowBase + r) * 128 + k0 + c];
            Bs[r][c] = W[(colBase + r) * 128 + k0 + c];
        }
        __syncthreads();
        #pragma unroll 8
        for (int kk = 0; kk < 32; kk++) {
            float a[4], b[4];
            #pragma unroll
            for (int i = 0; i < 4; i++) a[i] = As[ty + 16 * i][kk];
            #pragma unroll
            for (int j = 0; j < 4; j++) b[j] = Bs[tx + 16 * j][kk];
            #pragma unroll
            for (int i = 0; i < 4; i++)
                #pragma unroll
                for (int j = 0; j < 4; j++)
                    acc[i][j] = fmaf(a[i], b[j], acc[i][j]);
        }
        __syncthreads();
    }
    #pragma unroll
    for (int i = 0; i < 4; i++)
        #pragma unroll
        for (int j = 0; j < 4; j++)
            C[(rowBase + ty + 16 * i) * 128 + colBase + tx + 16 * j] = acc[i][j];
}

// Fused QKV projection: blockIdx.z selects which weight / output.
__global__ void qkv_kernel(const float* __restrict__ x,
                           const float* __restrict__ Wq,
                           const float* __restrict__ Wk,
                           const float* __restrict__ Wv) {
    const float* W = (blockIdx.z == 0) ? Wq : (blockIdx.z == 1) ? Wk : Wv;
    float* C = (blockIdx.z == 0) ? g_Q : (blockIdx.z == 1) ? g_K : g_V;
    gemm_tile(x, W, C);
}

// Output projection: out = AO @ Wo^T
__global__ void proj_kernel(const float* __restrict__ Wo, float* __restrict__ out) {
    gemm_tile(g_AO, Wo, out);
}

// ---------------------------------------------------------------------------
// Causal attention, DH=2. One block per (b,h). Two-pass softmax per query.
// Thread tid handles queries {tid, 1023-tid}: exactly 1025 keys per thread.
// ---------------------------------------------------------------------------
__global__ void __launch_bounds__(512) attn_kernel() {
    __shared__ float2 sK[TT];
    __shared__ float2 sV[TT];

    const int b = blockIdx.x >> 6;   // / HH
    const int h = blockIdx.x & 63;   // % HH
    const int base = b * TT;

    const float2* __restrict__ Qp = reinterpret_cast<const float2*>(g_Q);
    const float2* __restrict__ Kp = reinterpret_cast<const float2*>(g_K);
    const float2* __restrict__ Vp = reinterpret_cast<const float2*>(g_V);
    float2* __restrict__ Op = reinterpret_cast<float2*>(g_AO);

    for (int t = threadIdx.x; t < TT; t += 512) {
        sK[t] = Kp[(base + t) * 64 + h];
        sV[t] = Vp[(base + t) * 64 + h];
    }
    __syncthreads();

    // fold 1/(sqrt(DH)*temperature) and log2(e) into the query
    const float cf = 1.4426950408889634f / (1.4142135623730951f * 0.8f);

    #pragma unroll
    for (int qi = 0; qi < 2; qi++) {
        const int q = (qi == 0) ? (int)threadIdx.x : (TT - 1 - (int)threadIdx.x);
        const float2 qv = Qp[(base + q) * 64 + h];
        const float q0 = qv.x * cf;
        const float q1 = qv.y * cf;

        // Pass 1: row max (in log2 domain)
        float m = -1e30f;
        #pragma unroll 4
        for (int k = 0; k <= q; k++) {
            float2 kv = sK[k];
            float s = fmaf(q0, kv.x, q1 * kv.y);
            m = fmaxf(m, s);
        }

        // Pass 2: exp-sum and weighted V accumulate
        float l = 0.f, a0 = 0.f, a1 = 0.f;
        #pragma unroll 4
        for (int k = 0; k <= q; k++) {
            float2 kv = sK[k];
            float s = fmaf(q0, kv.x, fmaf(q1, kv.y, -m));
            float p = ex2f(s);
            float2 vv = sV[k];
            l += p;
            a0 = fmaf(p, vv.x, a0);
            a1 = fmaf(p, vv.y, a1);
        }

        const float inv = 1.0f / l;
        Op[(base + q) * 64 + h] = make_float2(a0 * inv, a1 * inv);
    }
}

extern "C" void kernel_launch(void* const* d_in, const int* in_sizes, int n_in,
                              void* d_out, int out_size) {
    const float* x  = (const float*)d_in[0];
    const float* Wq = (const float*)d_in[1];
    const float* Wk = (const float*)d_in[2];
    const float* Wv = (const float*)d_in[3];
    const float* Wo = (const float*)d_in[4];
    float* out = (float*)d_out;

    qkv_kernel<<<dim3(32, 2, 3), 256>>>(x, Wq, Wk, Wv);
    attn_kernel<<<BB * HH, 512>>>();
    proj_kernel<<<dim3(32, 2, 1), 256>>>(Wo, out);
}